// round 13
// baseline (speedup 1.0000x reference)
#include <cuda_runtime.h>
#include <cuda_bf16.h>
#include <cstdint>
#include <math.h>

#define Bb 2
#define Ss 2048
#define Ee 2048
#define NH 16
#define NKV 4
#define HD 128
#define WIN 1024
#define GQ (NH / NKV)
#define MR (Bb * Ss)   // 4096 rows
#define NQKV (NH * HD + 2 * NKV * HD)  // 3072

// ---------------------------------------------------------------------------
// Scratch (device globals; no allocation allowed)
// ---------------------------------------------------------------------------
__device__ __nv_bfloat16 g_xh[(size_t)MR * Ee],  g_xl[(size_t)MR * Ee];
__device__ __nv_bfloat16 g_aoh[(size_t)MR * Ee], g_aol[(size_t)MR * Ee];
__device__ __nv_bfloat16 g_wqkvh[(size_t)NQKV * Ee], g_wqkvl[(size_t)NQKV * Ee];
__device__ __nv_bfloat16 g_woh[(size_t)Ee * Ee],  g_wol[(size_t)Ee * Ee];

__device__ __nv_bfloat16 g_qh[(size_t)MR * NH * HD],  g_ql[(size_t)MR * NH * HD];
__device__ __nv_bfloat16 g_kh[(size_t)MR * NKV * HD], g_kl[(size_t)MR * NKV * HD];
__device__ __nv_bfloat16 g_vh[(size_t)MR * NKV * HD], g_vl[(size_t)MR * NKV * HD];

// ---------------------------------------------------------------------------
// PTX helpers
// ---------------------------------------------------------------------------
static __device__ __forceinline__ uint32_t smem_u32(const void* p) {
    uint32_t a;
    asm("{ .reg .u64 t; cvta.to.shared.u64 t, %1; cvt.u32.u64 %0, t; }" : "=r"(a) : "l"(p));
    return a;
}
static __device__ __forceinline__ void ldsm4(uint32_t* r, uint32_t addr) {
    asm volatile("ldmatrix.sync.aligned.m8n8.x4.shared.b16 {%0,%1,%2,%3}, [%4];"
                 : "=r"(r[0]), "=r"(r[1]), "=r"(r[2]), "=r"(r[3]) : "r"(addr));
}
static __device__ __forceinline__ void ldsm4t(uint32_t* r, uint32_t addr) {
    asm volatile("ldmatrix.sync.aligned.m8n8.x4.trans.shared.b16 {%0,%1,%2,%3}, [%4];"
                 : "=r"(r[0]), "=r"(r[1]), "=r"(r[2]), "=r"(r[3]) : "r"(addr));
}
static __device__ __forceinline__ void mma16816(float* d, const uint32_t* a, const uint32_t* b) {
    asm volatile(
        "mma.sync.aligned.m16n8k16.row.col.f32.bf16.bf16.f32 "
        "{%0,%1,%2,%3}, {%4,%5,%6,%7}, {%8,%9}, {%0,%1,%2,%3};"
        : "+f"(d[0]), "+f"(d[1]), "+f"(d[2]), "+f"(d[3])
        : "r"(a[0]), "r"(a[1]), "r"(a[2]), "r"(a[3]), "r"(b[0]), "r"(b[1]));
}

#define CP_ASYNC16(sa, gp) \
    asm volatile("cp.async.cg.shared.global [%0], [%1], 16;" :: "r"(sa), "l"(gp))
#define CP_COMMIT()  asm volatile("cp.async.commit_group;" ::: "memory")
#define CP_WAIT0()   asm volatile("cp.async.wait_group 0;" ::: "memory")
#define CP_WAIT1()   asm volatile("cp.async.wait_group 1;" ::: "memory")

static __device__ __forceinline__ uint32_t swoff(int r, int c) {
    return (uint32_t)(r * 64 + ((c ^ ((r >> 1) & 3)) << 4));
}

static __device__ __forceinline__ uint32_t packsplit(float a, float b, uint32_t& lo) {
    __nv_bfloat162 h = __floats2bfloat162_rn(a, b);
    float2 hf = __bfloat1622float2(h);
    __nv_bfloat162 l = __floats2bfloat162_rn(a - hf.x, b - hf.y);
    lo = *reinterpret_cast<uint32_t*>(&l);
    return *reinterpret_cast<uint32_t*>(&h);
}

// ---------------------------------------------------------------------------
// Fused fp32 -> bf16 hi/lo split for x | Wqkv | Wo in ONE launch.
// ---------------------------------------------------------------------------
#define NX4  (MR * Ee / 4)
#define NWQ4 (NH * HD * Ee / 4)
#define NWK4 (NKV * HD * Ee / 4)
#define NW4  (NQKV * Ee / 4)
#define NWO4 (Ee * Ee / 4)
#define NSPLIT4 (NX4 + NW4 + NWO4)

static __device__ __forceinline__ void do_split4(
    const float* src, __nv_bfloat16* dh, __nv_bfloat16* dl, int di)
{
    float4 v = *(const float4*)src;
    float vv[4] = {v.x, v.y, v.z, v.w};
    ushort4 hu, lu;
    unsigned short* hp = &hu.x;
    unsigned short* lp = &lu.x;
#pragma unroll
    for (int j = 0; j < 4; j++) {
        __nv_bfloat16 h = __float2bfloat16(vv[j]);
        __nv_bfloat16 l = __float2bfloat16(vv[j] - __bfloat162float(h));
        hp[j] = __bfloat16_as_ushort(h);
        lp[j] = __bfloat16_as_ushort(l);
    }
    ((ushort4*)dh)[di] = hu;
    ((ushort4*)dl)[di] = lu;
}

__global__ void split_all(const float* __restrict__ x,
                          const float* __restrict__ Wq,
                          const float* __restrict__ Wk,
                          const float* __restrict__ Wv,
                          const float* __restrict__ Wo,
                          __nv_bfloat16* __restrict__ xh, __nv_bfloat16* __restrict__ xl,
                          __nv_bfloat16* __restrict__ wh, __nv_bfloat16* __restrict__ wl,
                          __nv_bfloat16* __restrict__ woh, __nv_bfloat16* __restrict__ wol)
{
    int i = blockIdx.x * blockDim.x + threadIdx.x;
    if (i >= NSPLIT4) return;
    if (i < NX4) {
        do_split4(x + (size_t)i * 4, xh, xl, i);
    } else if (i < NX4 + NW4) {
        int w = i - NX4;
        const float* src;
        if (w < NWQ4)             src = Wq + (size_t)w * 4;
        else if (w < NWQ4 + NWK4) src = Wk + (size_t)(w - NWQ4) * 4;
        else                      src = Wv + (size_t)(w - NWQ4 - NWK4) * 4;
        do_split4(src, wh, wl, w);
    } else {
        int w = i - NX4 - NW4;
        do_split4(Wo + (size_t)w * 4, woh, wol, w);
    }
}

// ---------------------------------------------------------------------------
// Shared GEMM mainloop: 3-stage cp.async pipeline, wait_group 1.
// ---------------------------------------------------------------------------
#define GSTAGE 32768
#define GSMEM  (3 * GSTAGE)

static __device__ __forceinline__ void ld_tile32(
    uint32_t sdst, const __nv_bfloat16* gsrc, int K, int kt, int t)
{
#pragma unroll
    for (int i = 0; i < 2; i++) {
        int ci = t + i * 256;
        int r = ci >> 2, c = ci & 3;
        const char* gp = (const char*)(gsrc + (size_t)r * K + kt * 32 + c * 8);
        CP_ASYNC16(sdst + swoff(r, c), gp);
    }
}
static __device__ __forceinline__ void ld_stage(
    uint32_t sst, const __nv_bfloat16* Ahb, const __nv_bfloat16* Alb,
    const __nv_bfloat16* Bhb, const __nv_bfloat16* Blb, int K, int kt, int t)
{
    ld_tile32(sst + 0,     Ahb, K, kt, t);
    ld_tile32(sst + 8192,  Alb, K, kt, t);
    ld_tile32(sst + 16384, Bhb, K, kt, t);
    ld_tile32(sst + 24576, Blb, K, kt, t);
    CP_COMMIT();
}

static __device__ __forceinline__ void gemm_mainloop(
    uint32_t sb, const __nv_bfloat16* Ahb, const __nv_bfloat16* Alb,
    const __nv_bfloat16* Bhb, const __nv_bfloat16* Blb, int K, int t,
    float acc[2][8][4])
{
    const int lane = t & 31;
    const int wid  = t >> 5;
    const int wm   = (wid & 3) * 32;
    const int wn   = (wid >> 2) * 64;
    const int nchunk = K / 32;

    ld_stage(sb + 0 * GSTAGE, Ahb, Alb, Bhb, Blb, K, 0, t);
    if (1 < nchunk) ld_stage(sb + 1 * GSTAGE, Ahb, Alb, Bhb, Blb, K, 1, t);

    const int a_row  = lane & 15;
    const int a_cofs = lane >> 4;
    const int b_row  = (lane & 7) + ((lane & 16) ? 8 : 0);
    const int b_cofs = (lane >> 3) & 1;

    int slot = 0, nslot = 2;
    for (int kt = 0; kt < nchunk; kt++) {
        CP_WAIT1();
        __syncthreads();
        if (kt + 2 < nchunk) {
            ld_stage(sb + (uint32_t)nslot * GSTAGE, Ahb, Alb, Bhb, Blb, K, kt + 2, t);
        }
        const uint32_t so = sb + (uint32_t)slot * GSTAGE;
        slot = (slot == 2) ? 0 : slot + 1;
        nslot = (nslot == 2) ? 0 : nslot + 1;

#pragma unroll
        for (int ks = 0; ks < 2; ks++) {
            const int c = ks * 2;
            uint32_t ah[2][4], al[2][4];
#pragma unroll
            for (int mt = 0; mt < 2; mt++) {
                int r = wm + mt * 16 + a_row;
                ldsm4(ah[mt], so + 0    + swoff(r, c + a_cofs));
                ldsm4(al[mt], so + 8192 + swoff(r, c + a_cofs));
            }
#pragma unroll
            for (int pt = 0; pt < 4; pt++) {
                int r = wn + pt * 16 + b_row;
                uint32_t bh[4], bl[4];
                ldsm4(bh, so + 16384 + swoff(r, c + b_cofs));
                ldsm4(bl, so + 24576 + swoff(r, c + b_cofs));
#pragma unroll
                for (int mt = 0; mt < 2; mt++) {
#pragma unroll
                    for (int sub = 0; sub < 2; sub++) {
                        float* d = acc[mt][pt * 2 + sub];
                        mma16816(d, ah[mt], bh + sub * 2);
                        mma16816(d, ah[mt], bl + sub * 2);
                        mma16816(d, al[mt], bh + sub * 2);
                    }
                }
            }
        }
    }
    CP_WAIT0();
    __syncthreads();
}

// ---------------------------------------------------------------------------
// Plain GEMM (fp32 output) — output projection. 2 CTAs/SM.
// ---------------------------------------------------------------------------
__global__ void __launch_bounds__(256, 2) gemm_mma(
    const __nv_bfloat16* __restrict__ Ah, const __nv_bfloat16* __restrict__ Al,
    const __nv_bfloat16* __restrict__ Bh, const __nv_bfloat16* __restrict__ Bl,
    float* __restrict__ C, int M, int N, int K)
{
    extern __shared__ char rawsm[];
    const uint32_t sb = smem_u32(rawsm);
    const int t    = threadIdx.x;
    const int lane = t & 31;
    const int wid  = t >> 5;
    const int wm   = (wid & 3) * 32;
    const int wn   = (wid >> 2) * 64;
    const int bm = blockIdx.y, bn = blockIdx.x;

    float acc[2][8][4];
#pragma unroll
    for (int i = 0; i < 2; i++)
#pragma unroll
        for (int j = 0; j < 8; j++)
#pragma unroll
            for (int r = 0; r < 4; r++) acc[i][j][r] = 0.f;

    gemm_mainloop(sb, Ah + (size_t)bm * 128 * K, Al + (size_t)bm * 128 * K,
                  Bh + (size_t)bn * 128 * K, Bl + (size_t)bn * 128 * K, K, t, acc);

    const int gr = lane >> 2, tg = lane & 3;
#pragma unroll
    for (int mt = 0; mt < 2; mt++) {
#pragma unroll
        for (int nt = 0; nt < 8; nt++) {
            int row0 = bm * 128 + wm + mt * 16 + gr;
            int col  = bn * 128 + wn + nt * 8 + tg * 2;
            float* d = acc[mt][nt];
            *(float2*)(C + (size_t)row0 * N + col)       = make_float2(d[0], d[1]);
            *(float2*)(C + (size_t)(row0 + 8) * N + col) = make_float2(d[2], d[3]);
        }
    }
}

// ---------------------------------------------------------------------------
// Fused QKV GEMM + RoPE + scale + split epilogue. 2 CTAs/SM.
// ---------------------------------------------------------------------------
__global__ void __launch_bounds__(256, 2) gemm_qkv(
    const __nv_bfloat16* __restrict__ Ah, const __nv_bfloat16* __restrict__ Al,
    const __nv_bfloat16* __restrict__ Bh, const __nv_bfloat16* __restrict__ Bl,
    const float* __restrict__ cosT, const float* __restrict__ sinT,
    __nv_bfloat16* __restrict__ qh, __nv_bfloat16* __restrict__ ql,
    __nv_bfloat16* __restrict__ kh, __nv_bfloat16* __restrict__ kl,
    __nv_bfloat16* __restrict__ vh, __nv_bfloat16* __restrict__ vl)
{
    extern __shared__ char rawsm[];
    const uint32_t sb = smem_u32(rawsm);
    const int t    = threadIdx.x;
    const int lane = t & 31;
    const int wid  = t >> 5;
    const int wm   = (wid & 3) * 32;
    const int wn   = (wid >> 2) * 64;
    const int bm = blockIdx.y, bn = blockIdx.x;
    const int K = Ee;

    float acc[2][8][4];
#pragma unroll
    for (int i = 0; i < 2; i++)
#pragma unroll
        for (int j = 0; j < 8; j++)
#pragma unroll
            for (int r = 0; r < 4; r++) acc[i][j][r] = 0.f;

    gemm_mainloop(sb, Ah + (size_t)bm * 128 * K, Al + (size_t)bm * 128 * K,
                  Bh + (size_t)bn * 128 * K, Bl + (size_t)bn * 128 * K, K, t, acc);

    __nv_bfloat16 *dh, *dl;
    int nheads, hsel;
    bool dorope;
    float sc;
    if (bn < 16)      { dh = qh; dl = ql; nheads = NH;  hsel = bn;      dorope = true;  sc = 0.08838834764831845f; }
    else if (bn < 20) { dh = kh; dl = kl; nheads = NKV; hsel = bn - 16; dorope = true;  sc = 1.f; }
    else              { dh = vh; dl = vl; nheads = NKV; hsel = bn - 20; dorope = false; sc = 1.f; }

    float* es = (float*)rawsm;
    const int gr = lane >> 2, tg = lane & 3;

#pragma unroll
    for (int half = 0; half < 2; half++) {
        const int h0 = half * 64;
        __syncthreads();
        if ((wm & 64) == h0) {
#pragma unroll
            for (int mt = 0; mt < 2; mt++) {
                int r0 = (wm & 32) + mt * 16 + gr;
#pragma unroll
                for (int nt = 0; nt < 8; nt++) {
                    int col = wn + nt * 8 + tg * 2;
                    float* d = acc[mt][nt];
                    *(float2*)(es + r0 * 132 + col)       = make_float2(d[0], d[1]);
                    *(float2*)(es + (r0 + 8) * 132 + col) = make_float2(d[2], d[3]);
                }
            }
        }
        __syncthreads();
#pragma unroll
        for (int i = 0; i < 8; i++) {
            int p = t + i * 256;
            int r = p >> 5;
            int dd = (p & 31) * 2;
            int grow = bm * 128 + h0 + r;
            int s = grow & (Ss - 1);
            float2 xa = *(const float2*)(es + r * 132 + dd);
            float2 xb = *(const float2*)(es + r * 132 + dd + 64);
            float o1a, o1b, o2a, o2b;
            if (dorope) {
                float2 c1 = *(const float2*)(cosT + (size_t)s * HD + dd);
                float2 s1 = *(const float2*)(sinT + (size_t)s * HD + dd);
                float2 c2 = *(const float2*)(cosT + (size_t)s * HD + dd + 64);
                float2 s2 = *(const float2*)(sinT + (size_t)s * HD + dd + 64);
                o1a = xa.x * c1.x - xb.x * s1.x;
                o1b = xa.y * c1.y - xb.y * s1.y;
                o2a = xb.x * c2.x + xa.x * s2.x;
                o2b = xb.y * c2.y + xa.y * s2.y;
            } else {
                o1a = xa.x; o1b = xa.y; o2a = xb.x; o2b = xb.y;
            }
            o1a *= sc; o1b *= sc; o2a *= sc; o2b *= sc;
            size_t base = ((size_t)grow * nheads + hsel) * HD;
            uint32_t lo1, lo2;
            uint32_t hi1 = packsplit(o1a, o1b, lo1);
            uint32_t hi2 = packsplit(o2a, o2b, lo2);
            *(uint32_t*)(dh + base + dd)      = hi1;
            *(uint32_t*)(dl + base + dd)      = lo1;
            *(uint32_t*)(dh + base + dd + 64) = hi2;
            *(uint32_t*)(dl + base + dd + 64) = lo2;
        }
    }
}

// ---------------------------------------------------------------------------
// HMMA windowed-causal flash attention.
// LPT scheduling: qt mapped DESCENDING in blockIdx.x so the longest CTAs
// (18 j-tiles for qt>=8) launch first; short ones backfill.
// ---------------------------------------------------------------------------
#define FQH  0
#define FQL  32768
#define FST  65536
#define FSTG 65536
#define FLASH_SMEM (FST + 2 * FSTG)   // 196608

static __device__ __forceinline__ void flash_ld_q(
    uint32_t sq, const __nv_bfloat16* gq, int bs0, int h, int t)
{
#pragma unroll
    for (int i = 0; i < 8; i++) {
        int id = t + i * 256;
        int sub = id >> 9, rem = id & 511;
        int r = rem >> 2, c = rem & 3;
        const char* gp = (const char*)(gq + ((size_t)(bs0 + r) * NH + h) * HD + sub * 32 + c * 8);
        CP_ASYNC16(sq + sub * 8192 + swoff(r, c), gp);
    }
}
static __device__ __forceinline__ void flash_ld_kv(
    uint32_t sdst, const __nv_bfloat16* gsrc, int bs0, int hk, int t)
{
#pragma unroll
    for (int i = 0; i < 4; i++) {
        int id = t + i * 256;
        int sub = id >> 8, rem = id & 255;
        int r = rem >> 2, c = rem & 3;
        const char* gp = (const char*)(gsrc + ((size_t)(bs0 + r) * NKV + hk) * HD + sub * 32 + c * 8);
        CP_ASYNC16(sdst + sub * 4096 + swoff(r, c), gp);
    }
}

__global__ void __launch_bounds__(256) flash_mma(
    const __nv_bfloat16* __restrict__ qh, const __nv_bfloat16* __restrict__ ql,
    const __nv_bfloat16* __restrict__ kh, const __nv_bfloat16* __restrict__ kl,
    const __nv_bfloat16* __restrict__ vh, const __nv_bfloat16* __restrict__ vl,
    __nv_bfloat16* __restrict__ aoh, __nv_bfloat16* __restrict__ aol)
{
    extern __shared__ char rawsm[];
    const uint32_t sb = smem_u32(rawsm);

    const int t    = threadIdx.x;
    const int lane = t & 31;
    const int wid  = t >> 5;
    const int wm   = wid * 16;
    // LPT: longest work (largest qt) first
    const int qt = (int)gridDim.x - 1 - (int)blockIdx.x;
    const int h = blockIdx.y, b = blockIdx.z;
    const int hk = h / GQ;
    const int q0 = qt * 128;
    const int bs = b * Ss;

    const int a_row  = lane & 15;
    const int a_cofs = lane >> 4;
    const int b_row  = (lane & 7) + ((lane & 16) ? 8 : 0);
    const int b_cofs = (lane >> 3) & 1;
    const int v_row  = lane & 15;
    const int v_cofs = lane >> 4;

    float m0 = -1e30f, m1 = -1e30f, l0 = 0.f, l1 = 0.f;
    float o[16][4];
#pragma unroll
    for (int j = 0; j < 16; j++)
#pragma unroll
        for (int r = 0; r < 4; r++) o[j][r] = 0.f;

    int lo = q0 - (WIN - 1); if (lo < 0) lo = 0;
    const int jt0 = lo >> 6;
    const int jt1 = (q0 + 127) >> 6;

    flash_ld_q(sb + FQH, qh, bs + q0, h, t);
    flash_ld_q(sb + FQL, ql, bs + q0, h, t);
    {
        const uint32_t s0 = sb + FST + (uint32_t)(jt0 & 1) * FSTG;
        flash_ld_kv(s0 + 0,     kh, bs + jt0 * 64, hk, t);
        flash_ld_kv(s0 + 16384, kl, bs + jt0 * 64, hk, t);
        flash_ld_kv(s0 + 32768, vh, bs + jt0 * 64, hk, t);
        flash_ld_kv(s0 + 49152, vl, bs + jt0 * 64, hk, t);
    }
    CP_COMMIT();

    const int gi0 = q0 + wm + (lane >> 2);
    const int gi1 = gi0 + 8;
    const int colq = (lane & 3) * 2;

    for (int jt = jt0; jt <= jt1; jt++) {
        const int j0 = jt * 64;
        CP_WAIT0();
        __syncthreads();
        if (jt + 1 <= jt1) {
            const uint32_t sn = sb + FST + (uint32_t)((jt + 1) & 1) * FSTG;
            flash_ld_kv(sn + 0,     kh, bs + (jt + 1) * 64, hk, t);
            flash_ld_kv(sn + 16384, kl, bs + (jt + 1) * 64, hk, t);
            flash_ld_kv(sn + 32768, vh, bs + (jt + 1) * 64, hk, t);
            flash_ld_kv(sn + 49152, vl, bs + (jt + 1) * 64, hk, t);
            CP_COMMIT();
        }
        const uint32_t st = sb + FST + (uint32_t)(jt & 1) * FSTG;

        float s[8][4];
#pragma unroll
        for (int j = 0; j < 8; j++)
#pragma unroll
            for (int r = 0; r < 4; r++) s[j][r] = 0.f;

#pragma unroll
        for (int kc = 0; kc < 8; kc++) {
            const int sub = kc >> 1, cb = (kc & 1) * 2;
            uint32_t ah[4], al[4];
            uint32_t qa = sb + FQH + sub * 8192 + swoff(wm + a_row, cb + a_cofs);
            ldsm4(ah, qa);
            ldsm4(al, qa + 32768);
#pragma unroll
            for (int nt = 0; nt < 4; nt++) {
                uint32_t ka = st + sub * 4096 + swoff(nt * 16 + b_row, cb + b_cofs);
                uint32_t bh[4], bl[4];
                ldsm4(bh, ka);
                ldsm4(bl, ka + 16384);
#pragma unroll
                for (int su = 0; su < 2; su++) {
                    float* d = s[nt * 2 + su];
                    mma16816(d, ah, bh + su * 2);
                    mma16816(d, ah, bl + su * 2);
                    mma16816(d, al, bh + su * 2);
                }
            }
        }

        float mt0 = -1e30f, mt1 = -1e30f;
#pragma unroll
        for (int j = 0; j < 8; j++) {
            int c0 = j0 + j * 8 + colq;
#pragma unroll
            for (int e = 0; e < 2; e++) {
                int cc = c0 + e;
                int d0 = gi0 - cc, d1 = gi1 - cc;
                if (d0 < 0 || d0 >= WIN) s[j][e] = -1e30f;
                if (d1 < 0 || d1 >= WIN) s[j][2 + e] = -1e30f;
                mt0 = fmaxf(mt0, s[j][e]);
                mt1 = fmaxf(mt1, s[j][2 + e]);
            }
        }
#pragma unroll
        for (int off = 1; off <= 2; off <<= 1) {
            mt0 = fmaxf(mt0, __shfl_xor_sync(0xffffffffu, mt0, off));
            mt1 = fmaxf(mt1, __shfl_xor_sync(0xffffffffu, mt1, off));
        }
        float mn0 = fmaxf(m0, mt0), mn1 = fmaxf(m1, mt1);
        float al0 = __expf(m0 - mn0), al1 = __expf(m1 - mn1);
        m0 = mn0; m1 = mn1;

        float rs0 = 0.f, rs1 = 0.f;
#pragma unroll
        for (int j = 0; j < 8; j++) {
#pragma unroll
            for (int e = 0; e < 2; e++) {
                float p0 = (s[j][e]     > -1e29f) ? __expf(s[j][e]     - mn0) : 0.f;
                float p1 = (s[j][2 + e] > -1e29f) ? __expf(s[j][2 + e] - mn1) : 0.f;
                s[j][e] = p0; s[j][2 + e] = p1;
                rs0 += p0; rs1 += p1;
            }
        }
#pragma unroll
        for (int off = 1; off <= 2; off <<= 1) {
            rs0 += __shfl_xor_sync(0xffffffffu, rs0, off);
            rs1 += __shfl_xor_sync(0xffffffffu, rs1, off);
        }
        l0 = l0 * al0 + rs0;
        l1 = l1 * al1 + rs1;
#pragma unroll
        for (int j = 0; j < 16; j++) {
            o[j][0] *= al0; o[j][1] *= al0;
            o[j][2] *= al1; o[j][3] *= al1;
        }

#pragma unroll
        for (int kc2 = 0; kc2 < 4; kc2++) {
            uint32_t phi[4], plo[4];
            phi[0] = packsplit(s[2 * kc2][0],     s[2 * kc2][1],     plo[0]);
            phi[1] = packsplit(s[2 * kc2][2],     s[2 * kc2][3],     plo[1]);
            phi[2] = packsplit(s[2 * kc2 + 1][0], s[2 * kc2 + 1][1], plo[2]);
            phi[3] = packsplit(s[2 * kc2 + 1][2], s[2 * kc2 + 1][3], plo[3]);
#pragma unroll
            for (int nt = 0; nt < 8; nt++) {
                const int sub = nt >> 1, cb = (nt & 1) * 2;
                uint32_t va = st + 32768 + sub * 4096
                            + swoff(kc2 * 16 + v_row, cb + v_cofs);
                uint32_t vhf[4], vlf[4];
                ldsm4t(vhf, va);
                ldsm4t(vlf, va + 16384);
#pragma unroll
                for (int su = 0; su < 2; su++) {
                    float* d = o[nt * 2 + su];
                    mma16816(d, phi, vhf + su * 2);
                    mma16816(d, phi, vlf + su * 2);
                    mma16816(d, plo, vhf + su * 2);
                }
            }
        }
    }

    float inv0 = 1.f / l0, inv1 = 1.f / l1;
#pragma unroll
    for (int j = 0; j < 16; j++) {
        int col = j * 8 + colq;
        size_t b0 = ((size_t)(bs + gi0) * NH + h) * HD + col;
        size_t b1 = ((size_t)(bs + gi1) * NH + h) * HD + col;
        uint32_t lo0, lo1v;
        uint32_t hi0 = packsplit(o[j][0] * inv0, o[j][1] * inv0, lo0);
        uint32_t hi1 = packsplit(o[j][2] * inv1, o[j][3] * inv1, lo1v);
        *(uint32_t*)(aoh + b0) = hi0;
        *(uint32_t*)(aol + b0) = lo0;
        *(uint32_t*)(aoh + b1) = hi1;
        *(uint32_t*)(aol + b1) = lo1v;
    }
}

// ---------------------------------------------------------------------------
extern "C" void kernel_launch(void* const* d_in, const int* in_sizes, int n_in,
                              void* d_out, int out_size)
{
    const float* x    = (const float*)d_in[0];
    const float* cosT = (const float*)d_in[1];
    const float* sinT = (const float*)d_in[2];
    const float* Wq   = (const float*)d_in[3];
    const float* Wk   = (const float*)d_in[4];
    const float* Wv   = (const float*)d_in[5];
    const float* Wo   = (const float*)d_in[6];
    float* out = (float*)d_out;

    void *pxh, *pxl, *paoh, *paol, *pwh, *pwl, *pwoh, *pwol;
    void *pqh, *pql, *pkh, *pkl, *pvh, *pvl;
    cudaGetSymbolAddress(&pxh, g_xh);   cudaGetSymbolAddress(&pxl, g_xl);
    cudaGetSymbolAddress(&paoh, g_aoh); cudaGetSymbolAddress(&paol, g_aol);
    cudaGetSymbolAddress(&pwh, g_wqkvh); cudaGetSymbolAddress(&pwl, g_wqkvl);
    cudaGetSymbolAddress(&pwoh, g_woh); cudaGetSymbolAddress(&pwol, g_wol);
    cudaGetSymbolAddress(&pqh, g_qh);  cudaGetSymbolAddress(&pql, g_ql);
    cudaGetSymbolAddress(&pkh, g_kh);  cudaGetSymbolAddress(&pkl, g_kl);
    cudaGetSymbolAddress(&pvh, g_vh);  cudaGetSymbolAddress(&pvl, g_vl);

    __nv_bfloat16 *xh = (__nv_bfloat16*)pxh,   *xl = (__nv_bfloat16*)pxl;
    __nv_bfloat16 *aoh = (__nv_bfloat16*)paoh, *aol = (__nv_bfloat16*)paol;
    __nv_bfloat16 *wh = (__nv_bfloat16*)pwh,   *wl = (__nv_bfloat16*)pwl;
    __nv_bfloat16 *woh = (__nv_bfloat16*)pwoh, *wol = (__nv_bfloat16*)pwol;
    __nv_bfloat16 *qhp = (__nv_bfloat16*)pqh,  *qlp = (__nv_bfloat16*)pql;
    __nv_bfloat16 *khp = (__nv_bfloat16*)pkh,  *klp = (__nv_bfloat16*)pkl;
    __nv_bfloat16 *vhp = (__nv_bfloat16*)pvh,  *vlp = (__nv_bfloat16*)pvl;

    split_all<<<(NSPLIT4 + 255) / 256, 256>>>(x, Wq, Wk, Wv, Wo,
                                              xh, xl, wh, wl, woh, wol);

    cudaFuncSetAttribute(gemm_qkv, cudaFuncAttributeMaxDynamicSharedMemorySize, GSMEM);
    cudaFuncSetAttribute(gemm_mma, cudaFuncAttributeMaxDynamicSharedMemorySize, GSMEM);

    gemm_qkv<<<dim3(NQKV / 128, MR / 128), 256, GSMEM>>>(
        xh, xl, wh, wl, cosT, sinT, qhp, qlp, khp, klp, vhp, vlp);

    cudaFuncSetAttribute(flash_mma, cudaFuncAttributeMaxDynamicSharedMemorySize, FLASH_SMEM);
    flash_mma<<<dim3(Ss / 128, NH, Bb), 256, FLASH_SMEM>>>(
        qhp, qlp, khp, klp, vhp, vlp, aoh, aol);

    gemm_mma<<<dim3(Ee / 128, MR / 128), 256, GSMEM>>>(aoh, aol, woh, wol, out, MR, Ee, Ee);
}

// round 14
// speedup vs baseline: 1.0179x; 1.0179x over previous
#include <cuda_runtime.h>
#include <cuda_bf16.h>
#include <cstdint>
#include <math.h>

#define Bb 2
#define Ss 2048
#define Ee 2048
#define NH 16
#define NKV 4
#define HD 128
#define WIN 1024
#define GQ (NH / NKV)
#define MR (Bb * Ss)   // 4096 rows
#define NQKV (NH * HD + 2 * NKV * HD)  // 3072

// ---------------------------------------------------------------------------
// Scratch (device globals; no allocation allowed)
// ---------------------------------------------------------------------------
__device__ __nv_bfloat16 g_xh[(size_t)MR * Ee],  g_xl[(size_t)MR * Ee];
__device__ __nv_bfloat16 g_aoh[(size_t)MR * Ee], g_aol[(size_t)MR * Ee];
__device__ __nv_bfloat16 g_wqkvh[(size_t)NQKV * Ee], g_wqkvl[(size_t)NQKV * Ee];
__device__ __nv_bfloat16 g_woh[(size_t)Ee * Ee],  g_wol[(size_t)Ee * Ee];

__device__ __nv_bfloat16 g_qh[(size_t)MR * NH * HD],  g_ql[(size_t)MR * NH * HD];
__device__ __nv_bfloat16 g_kh[(size_t)MR * NKV * HD], g_kl[(size_t)MR * NKV * HD];
__device__ __nv_bfloat16 g_vh[(size_t)MR * NKV * HD], g_vl[(size_t)MR * NKV * HD];

// ---------------------------------------------------------------------------
// PTX helpers
// ---------------------------------------------------------------------------
static __device__ __forceinline__ uint32_t smem_u32(const void* p) {
    uint32_t a;
    asm("{ .reg .u64 t; cvta.to.shared.u64 t, %1; cvt.u32.u64 %0, t; }" : "=r"(a) : "l"(p));
    return a;
}
static __device__ __forceinline__ void ldsm4(uint32_t* r, uint32_t addr) {
    asm volatile("ldmatrix.sync.aligned.m8n8.x4.shared.b16 {%0,%1,%2,%3}, [%4];"
                 : "=r"(r[0]), "=r"(r[1]), "=r"(r[2]), "=r"(r[3]) : "r"(addr));
}
static __device__ __forceinline__ void ldsm4t(uint32_t* r, uint32_t addr) {
    asm volatile("ldmatrix.sync.aligned.m8n8.x4.trans.shared.b16 {%0,%1,%2,%3}, [%4];"
                 : "=r"(r[0]), "=r"(r[1]), "=r"(r[2]), "=r"(r[3]) : "r"(addr));
}
static __device__ __forceinline__ void mma16816(float* d, const uint32_t* a, const uint32_t* b) {
    asm volatile(
        "mma.sync.aligned.m16n8k16.row.col.f32.bf16.bf16.f32 "
        "{%0,%1,%2,%3}, {%4,%5,%6,%7}, {%8,%9}, {%0,%1,%2,%3};"
        : "+f"(d[0]), "+f"(d[1]), "+f"(d[2]), "+f"(d[3])
        : "r"(a[0]), "r"(a[1]), "r"(a[2]), "r"(a[3]), "r"(b[0]), "r"(b[1]));
}

#define CP_ASYNC16(sa, gp) \
    asm volatile("cp.async.cg.shared.global [%0], [%1], 16;" :: "r"(sa), "l"(gp))
#define CP_COMMIT()  asm volatile("cp.async.commit_group;" ::: "memory")
#define CP_WAIT0()   asm volatile("cp.async.wait_group 0;" ::: "memory")
#define CP_WAIT1()   asm volatile("cp.async.wait_group 1;" ::: "memory")

static __device__ __forceinline__ uint32_t swoff(int r, int c) {
    return (uint32_t)(r * 64 + ((c ^ ((r >> 1) & 3)) << 4));
}

static __device__ __forceinline__ uint32_t packsplit(float a, float b, uint32_t& lo) {
    __nv_bfloat162 h = __floats2bfloat162_rn(a, b);
    float2 hf = __bfloat1622float2(h);
    __nv_bfloat162 l = __floats2bfloat162_rn(a - hf.x, b - hf.y);
    lo = *reinterpret_cast<uint32_t*>(&l);
    return *reinterpret_cast<uint32_t*>(&h);
}

// ---------------------------------------------------------------------------
// Fused fp32 -> bf16 hi/lo split for x | Wqkv | Wo in ONE launch.
// ---------------------------------------------------------------------------
#define NX4  (MR * Ee / 4)
#define NWQ4 (NH * HD * Ee / 4)
#define NWK4 (NKV * HD * Ee / 4)
#define NW4  (NQKV * Ee / 4)
#define NWO4 (Ee * Ee / 4)
#define NSPLIT4 (NX4 + NW4 + NWO4)

static __device__ __forceinline__ void do_split4(
    const float* src, __nv_bfloat16* dh, __nv_bfloat16* dl, int di)
{
    float4 v = *(const float4*)src;
    float vv[4] = {v.x, v.y, v.z, v.w};
    ushort4 hu, lu;
    unsigned short* hp = &hu.x;
    unsigned short* lp = &lu.x;
#pragma unroll
    for (int j = 0; j < 4; j++) {
        __nv_bfloat16 h = __float2bfloat16(vv[j]);
        __nv_bfloat16 l = __float2bfloat16(vv[j] - __bfloat162float(h));
        hp[j] = __bfloat16_as_ushort(h);
        lp[j] = __bfloat16_as_ushort(l);
    }
    ((ushort4*)dh)[di] = hu;
    ((ushort4*)dl)[di] = lu;
}

__global__ void split_all(const float* __restrict__ x,
                          const float* __restrict__ Wq,
                          const float* __restrict__ Wk,
                          const float* __restrict__ Wv,
                          const float* __restrict__ Wo,
                          __nv_bfloat16* __restrict__ xh, __nv_bfloat16* __restrict__ xl,
                          __nv_bfloat16* __restrict__ wh, __nv_bfloat16* __restrict__ wl,
                          __nv_bfloat16* __restrict__ woh, __nv_bfloat16* __restrict__ wol)
{
    int i = blockIdx.x * blockDim.x + threadIdx.x;
    if (i >= NSPLIT4) return;
    if (i < NX4) {
        do_split4(x + (size_t)i * 4, xh, xl, i);
    } else if (i < NX4 + NW4) {
        int w = i - NX4;
        const float* src;
        if (w < NWQ4)             src = Wq + (size_t)w * 4;
        else if (w < NWQ4 + NWK4) src = Wk + (size_t)(w - NWQ4) * 4;
        else                      src = Wv + (size_t)(w - NWQ4 - NWK4) * 4;
        do_split4(src, wh, wl, w);
    } else {
        int w = i - NX4 - NW4;
        do_split4(Wo + (size_t)w * 4, woh, wol, w);
    }
}

// ---------------------------------------------------------------------------
// GEMM mainloop: 128 threads (4 warps), warp tile 64x64, 3-stage cp.async.
// Per-warp per-k16: 16 ldsm / 96 mma = 24 MAC/B (crossbar relief).
// ---------------------------------------------------------------------------
#define GSTAGE 32768
#define GSMEM  (3 * GSTAGE)

static __device__ __forceinline__ void ld_tile32(
    uint32_t sdst, const __nv_bfloat16* gsrc, int K, int kt, int t)
{
#pragma unroll
    for (int i = 0; i < 4; i++) {
        int ci = t + i * 128;            // 0..511 : 128 rows x 4 chunks
        int r = ci >> 2, c = ci & 3;
        const char* gp = (const char*)(gsrc + (size_t)r * K + kt * 32 + c * 8);
        CP_ASYNC16(sdst + swoff(r, c), gp);
    }
}
static __device__ __forceinline__ void ld_stage(
    uint32_t sst, const __nv_bfloat16* Ahb, const __nv_bfloat16* Alb,
    const __nv_bfloat16* Bhb, const __nv_bfloat16* Blb, int K, int kt, int t)
{
    ld_tile32(sst + 0,     Ahb, K, kt, t);
    ld_tile32(sst + 8192,  Alb, K, kt, t);
    ld_tile32(sst + 16384, Bhb, K, kt, t);
    ld_tile32(sst + 24576, Blb, K, kt, t);
    CP_COMMIT();
}

static __device__ __forceinline__ void gemm_mainloop(
    uint32_t sb, const __nv_bfloat16* Ahb, const __nv_bfloat16* Alb,
    const __nv_bfloat16* Bhb, const __nv_bfloat16* Blb, int K, int t,
    float acc[4][8][4])
{
    const int lane = t & 31;
    const int wid  = t >> 5;               // 0..3
    const int wm   = (wid & 1) * 64;
    const int wn   = (wid >> 1) * 64;
    const int nchunk = K / 32;

    ld_stage(sb + 0 * GSTAGE, Ahb, Alb, Bhb, Blb, K, 0, t);
    if (1 < nchunk) ld_stage(sb + 1 * GSTAGE, Ahb, Alb, Bhb, Blb, K, 1, t);

    const int a_row  = lane & 15;
    const int a_cofs = lane >> 4;
    const int b_row  = (lane & 7) + ((lane & 16) ? 8 : 0);
    const int b_cofs = (lane >> 3) & 1;

    int slot = 0, nslot = 2;
    for (int kt = 0; kt < nchunk; kt++) {
        CP_WAIT1();
        __syncthreads();
        if (kt + 2 < nchunk) {
            ld_stage(sb + (uint32_t)nslot * GSTAGE, Ahb, Alb, Bhb, Blb, K, kt + 2, t);
        }
        const uint32_t so = sb + (uint32_t)slot * GSTAGE;
        slot = (slot == 2) ? 0 : slot + 1;
        nslot = (nslot == 2) ? 0 : nslot + 1;

#pragma unroll
        for (int ks = 0; ks < 2; ks++) {
            const int c = ks * 2;
            uint32_t ah[4][4], al[4][4];
#pragma unroll
            for (int mt = 0; mt < 4; mt++) {
                int r = wm + mt * 16 + a_row;
                ldsm4(ah[mt], so + 0    + swoff(r, c + a_cofs));
                ldsm4(al[mt], so + 8192 + swoff(r, c + a_cofs));
            }
#pragma unroll
            for (int pt = 0; pt < 4; pt++) {
                int r = wn + pt * 16 + b_row;
                uint32_t bh[4], bl[4];
                ldsm4(bh, so + 16384 + swoff(r, c + b_cofs));
                ldsm4(bl, so + 24576 + swoff(r, c + b_cofs));
#pragma unroll
                for (int mt = 0; mt < 4; mt++) {
#pragma unroll
                    for (int sub = 0; sub < 2; sub++) {
                        float* d = acc[mt][pt * 2 + sub];
                        mma16816(d, ah[mt], bh + sub * 2);
                        mma16816(d, ah[mt], bl + sub * 2);
                        mma16816(d, al[mt], bh + sub * 2);
                    }
                }
            }
        }
    }
    CP_WAIT0();
    __syncthreads();
}

// ---------------------------------------------------------------------------
// Plain GEMM (fp32 output) — output projection. 128 threads, 2 CTAs/SM.
// ---------------------------------------------------------------------------
__global__ void __launch_bounds__(128, 2) gemm_mma(
    const __nv_bfloat16* __restrict__ Ah, const __nv_bfloat16* __restrict__ Al,
    const __nv_bfloat16* __restrict__ Bh, const __nv_bfloat16* __restrict__ Bl,
    float* __restrict__ C, int M, int N, int K)
{
    extern __shared__ char rawsm[];
    const uint32_t sb = smem_u32(rawsm);
    const int t    = threadIdx.x;
    const int lane = t & 31;
    const int wid  = t >> 5;
    const int wm   = (wid & 1) * 64;
    const int wn   = (wid >> 1) * 64;
    const int bm = blockIdx.y, bn = blockIdx.x;

    float acc[4][8][4];
#pragma unroll
    for (int i = 0; i < 4; i++)
#pragma unroll
        for (int j = 0; j < 8; j++)
#pragma unroll
            for (int r = 0; r < 4; r++) acc[i][j][r] = 0.f;

    gemm_mainloop(sb, Ah + (size_t)bm * 128 * K, Al + (size_t)bm * 128 * K,
                  Bh + (size_t)bn * 128 * K, Bl + (size_t)bn * 128 * K, K, t, acc);

    const int gr = lane >> 2, tg = lane & 3;
#pragma unroll
    for (int mt = 0; mt < 4; mt++) {
#pragma unroll
        for (int nt = 0; nt < 8; nt++) {
            int row0 = bm * 128 + wm + mt * 16 + gr;
            int col  = bn * 128 + wn + nt * 8 + tg * 2;
            float* d = acc[mt][nt];
            *(float2*)(C + (size_t)row0 * N + col)       = make_float2(d[0], d[1]);
            *(float2*)(C + (size_t)(row0 + 8) * N + col) = make_float2(d[2], d[3]);
        }
    }
}

// ---------------------------------------------------------------------------
// Fused QKV GEMM + RoPE + scale + split epilogue. 128 threads, 2 CTAs/SM.
// ---------------------------------------------------------------------------
__global__ void __launch_bounds__(128, 2) gemm_qkv(
    const __nv_bfloat16* __restrict__ Ah, const __nv_bfloat16* __restrict__ Al,
    const __nv_bfloat16* __restrict__ Bh, const __nv_bfloat16* __restrict__ Bl,
    const float* __restrict__ cosT, const float* __restrict__ sinT,
    __nv_bfloat16* __restrict__ qh, __nv_bfloat16* __restrict__ ql,
    __nv_bfloat16* __restrict__ kh, __nv_bfloat16* __restrict__ kl,
    __nv_bfloat16* __restrict__ vh, __nv_bfloat16* __restrict__ vl)
{
    extern __shared__ char rawsm[];
    const uint32_t sb = smem_u32(rawsm);
    const int t    = threadIdx.x;
    const int lane = t & 31;
    const int wid  = t >> 5;
    const int wm   = (wid & 1) * 64;
    const int wn   = (wid >> 1) * 64;
    const int bm = blockIdx.y, bn = blockIdx.x;
    const int K = Ee;

    float acc[4][8][4];
#pragma unroll
    for (int i = 0; i < 4; i++)
#pragma unroll
        for (int j = 0; j < 8; j++)
#pragma unroll
            for (int r = 0; r < 4; r++) acc[i][j][r] = 0.f;

    gemm_mainloop(sb, Ah + (size_t)bm * 128 * K, Al + (size_t)bm * 128 * K,
                  Bh + (size_t)bn * 128 * K, Bl + (size_t)bn * 128 * K, K, t, acc);

    __nv_bfloat16 *dh, *dl;
    int nheads, hsel;
    bool dorope;
    float sc;
    if (bn < 16)      { dh = qh; dl = ql; nheads = NH;  hsel = bn;      dorope = true;  sc = 0.08838834764831845f; }
    else if (bn < 20) { dh = kh; dl = kl; nheads = NKV; hsel = bn - 16; dorope = true;  sc = 1.f; }
    else              { dh = vh; dl = vl; nheads = NKV; hsel = bn - 20; dorope = false; sc = 1.f; }

    float* es = (float*)rawsm;   // 64 x 132 staging
    const int gr = lane >> 2, tg = lane & 3;

#pragma unroll
    for (int half = 0; half < 2; half++) {
        const int h0 = half * 64;
        __syncthreads();
        // warps whose 64-row span is this half stage their 64x64 block
        if (wm == h0) {
#pragma unroll
            for (int mt = 0; mt < 4; mt++) {
                int r0 = mt * 16 + gr;
#pragma unroll
                for (int nt = 0; nt < 8; nt++) {
                    int col = wn + nt * 8 + tg * 2;
                    float* d = acc[mt][nt];
                    *(float2*)(es + r0 * 132 + col)       = make_float2(d[0], d[1]);
                    *(float2*)(es + (r0 + 8) * 132 + col) = make_float2(d[2], d[3]);
                }
            }
        }
        __syncthreads();
        // rope + split + store: 64 rows x 32 even-d groups = 2048 units, 128 thr
#pragma unroll
        for (int i = 0; i < 16; i++) {
            int p = t + i * 128;
            int r = p >> 5;
            int dd = (p & 31) * 2;
            int grow = bm * 128 + h0 + r;
            int s = grow & (Ss - 1);
            float2 xa = *(const float2*)(es + r * 132 + dd);
            float2 xb = *(const float2*)(es + r * 132 + dd + 64);
            float o1a, o1b, o2a, o2b;
            if (dorope) {
                float2 c1 = *(const float2*)(cosT + (size_t)s * HD + dd);
                float2 s1 = *(const float2*)(sinT + (size_t)s * HD + dd);
                float2 c2 = *(const float2*)(cosT + (size_t)s * HD + dd + 64);
                float2 s2 = *(const float2*)(sinT + (size_t)s * HD + dd + 64);
                o1a = xa.x * c1.x - xb.x * s1.x;
                o1b = xa.y * c1.y - xb.y * s1.y;
                o2a = xb.x * c2.x + xa.x * s2.x;
                o2b = xb.y * c2.y + xa.y * s2.y;
            } else {
                o1a = xa.x; o1b = xa.y; o2a = xb.x; o2b = xb.y;
            }
            o1a *= sc; o1b *= sc; o2a *= sc; o2b *= sc;
            size_t base = ((size_t)grow * nheads + hsel) * HD;
            uint32_t lo1, lo2;
            uint32_t hi1 = packsplit(o1a, o1b, lo1);
            uint32_t hi2 = packsplit(o2a, o2b, lo2);
            *(uint32_t*)(dh + base + dd)      = hi1;
            *(uint32_t*)(dl + base + dd)      = lo1;
            *(uint32_t*)(dh + base + dd + 64) = hi2;
            *(uint32_t*)(dl + base + dd + 64) = lo2;
        }
    }
}

// ---------------------------------------------------------------------------
// HMMA windowed-causal flash attention (unchanged passing version, LPT remap)
// ---------------------------------------------------------------------------
#define FQH  0
#define FQL  32768
#define FST  65536
#define FSTG 65536
#define FLASH_SMEM (FST + 2 * FSTG)   // 196608

static __device__ __forceinline__ void flash_ld_q(
    uint32_t sq, const __nv_bfloat16* gq, int bs0, int h, int t)
{
#pragma unroll
    for (int i = 0; i < 8; i++) {
        int id = t + i * 256;
        int sub = id >> 9, rem = id & 511;
        int r = rem >> 2, c = rem & 3;
        const char* gp = (const char*)(gq + ((size_t)(bs0 + r) * NH + h) * HD + sub * 32 + c * 8);
        CP_ASYNC16(sq + sub * 8192 + swoff(r, c), gp);
    }
}
static __device__ __forceinline__ void flash_ld_kv(
    uint32_t sdst, const __nv_bfloat16* gsrc, int bs0, int hk, int t)
{
#pragma unroll
    for (int i = 0; i < 4; i++) {
        int id = t + i * 256;
        int sub = id >> 8, rem = id & 255;
        int r = rem >> 2, c = rem & 3;
        const char* gp = (const char*)(gsrc + ((size_t)(bs0 + r) * NKV + hk) * HD + sub * 32 + c * 8);
        CP_ASYNC16(sdst + sub * 4096 + swoff(r, c), gp);
    }
}

__global__ void __launch_bounds__(256) flash_mma(
    const __nv_bfloat16* __restrict__ qh, const __nv_bfloat16* __restrict__ ql,
    const __nv_bfloat16* __restrict__ kh, const __nv_bfloat16* __restrict__ kl,
    const __nv_bfloat16* __restrict__ vh, const __nv_bfloat16* __restrict__ vl,
    __nv_bfloat16* __restrict__ aoh, __nv_bfloat16* __restrict__ aol)
{
    extern __shared__ char rawsm[];
    const uint32_t sb = smem_u32(rawsm);

    const int t    = threadIdx.x;
    const int lane = t & 31;
    const int wid  = t >> 5;
    const int wm   = wid * 16;
    const int qt = (int)gridDim.x - 1 - (int)blockIdx.x;
    const int h = blockIdx.y, b = blockIdx.z;
    const int hk = h / GQ;
    const int q0 = qt * 128;
    const int bs = b * Ss;

    const int a_row  = lane & 15;
    const int a_cofs = lane >> 4;
    const int b_row  = (lane & 7) + ((lane & 16) ? 8 : 0);
    const int b_cofs = (lane >> 3) & 1;
    const int v_row  = lane & 15;
    const int v_cofs = lane >> 4;

    float m0 = -1e30f, m1 = -1e30f, l0 = 0.f, l1 = 0.f;
    float o[16][4];
#pragma unroll
    for (int j = 0; j < 16; j++)
#pragma unroll
        for (int r = 0; r < 4; r++) o[j][r] = 0.f;

    int lo = q0 - (WIN - 1); if (lo < 0) lo = 0;
    const int jt0 = lo >> 6;
    const int jt1 = (q0 + 127) >> 6;

    flash_ld_q(sb + FQH, qh, bs + q0, h, t);
    flash_ld_q(sb + FQL, ql, bs + q0, h, t);
    {
        const uint32_t s0 = sb + FST + (uint32_t)(jt0 & 1) * FSTG;
        flash_ld_kv(s0 + 0,     kh, bs + jt0 * 64, hk, t);
        flash_ld_kv(s0 + 16384, kl, bs + jt0 * 64, hk, t);
        flash_ld_kv(s0 + 32768, vh, bs + jt0 * 64, hk, t);
        flash_ld_kv(s0 + 49152, vl, bs + jt0 * 64, hk, t);
    }
    CP_COMMIT();

    const int gi0 = q0 + wm + (lane >> 2);
    const int gi1 = gi0 + 8;
    const int colq = (lane & 3) * 2;

    for (int jt = jt0; jt <= jt1; jt++) {
        const int j0 = jt * 64;
        CP_WAIT0();
        __syncthreads();
        if (jt + 1 <= jt1) {
            const uint32_t sn = sb + FST + (uint32_t)((jt + 1) & 1) * FSTG;
            flash_ld_kv(sn + 0,     kh, bs + (jt + 1) * 64, hk, t);
            flash_ld_kv(sn + 16384, kl, bs + (jt + 1) * 64, hk, t);
            flash_ld_kv(sn + 32768, vh, bs + (jt + 1) * 64, hk, t);
            flash_ld_kv(sn + 49152, vl, bs + (jt + 1) * 64, hk, t);
            CP_COMMIT();
        }
        const uint32_t st = sb + FST + (uint32_t)(jt & 1) * FSTG;

        float s[8][4];
#pragma unroll
        for (int j = 0; j < 8; j++)
#pragma unroll
            for (int r = 0; r < 4; r++) s[j][r] = 0.f;

#pragma unroll
        for (int kc = 0; kc < 8; kc++) {
            const int sub = kc >> 1, cb = (kc & 1) * 2;
            uint32_t ah[4], al[4];
            uint32_t qa = sb + FQH + sub * 8192 + swoff(wm + a_row, cb + a_cofs);
            ldsm4(ah, qa);
            ldsm4(al, qa + 32768);
#pragma unroll
            for (int nt = 0; nt < 4; nt++) {
                uint32_t ka = st + sub * 4096 + swoff(nt * 16 + b_row, cb + b_cofs);
                uint32_t bh[4], bl[4];
                ldsm4(bh, ka);
                ldsm4(bl, ka + 16384);
#pragma unroll
                for (int su = 0; su < 2; su++) {
                    float* d = s[nt * 2 + su];
                    mma16816(d, ah, bh + su * 2);
                    mma16816(d, ah, bl + su * 2);
                    mma16816(d, al, bh + su * 2);
                }
            }
        }

        float mt0 = -1e30f, mt1 = -1e30f;
#pragma unroll
        for (int j = 0; j < 8; j++) {
            int c0 = j0 + j * 8 + colq;
#pragma unroll
            for (int e = 0; e < 2; e++) {
                int cc = c0 + e;
                int d0 = gi0 - cc, d1 = gi1 - cc;
                if (d0 < 0 || d0 >= WIN) s[j][e] = -1e30f;
                if (d1 < 0 || d1 >= WIN) s[j][2 + e] = -1e30f;
                mt0 = fmaxf(mt0, s[j][e]);
                mt1 = fmaxf(mt1, s[j][2 + e]);
            }
        }
#pragma unroll
        for (int off = 1; off <= 2; off <<= 1) {
            mt0 = fmaxf(mt0, __shfl_xor_sync(0xffffffffu, mt0, off));
            mt1 = fmaxf(mt1, __shfl_xor_sync(0xffffffffu, mt1, off));
        }
        float mn0 = fmaxf(m0, mt0), mn1 = fmaxf(m1, mt1);
        float al0 = __expf(m0 - mn0), al1 = __expf(m1 - mn1);
        m0 = mn0; m1 = mn1;

        float rs0 = 0.f, rs1 = 0.f;
#pragma unroll
        for (int j = 0; j < 8; j++) {
#pragma unroll
            for (int e = 0; e < 2; e++) {
                float p0 = (s[j][e]     > -1e29f) ? __expf(s[j][e]     - mn0) : 0.f;
                float p1 = (s[j][2 + e] > -1e29f) ? __expf(s[j][2 + e] - mn1) : 0.f;
                s[j][e] = p0; s[j][2 + e] = p1;
                rs0 += p0; rs1 += p1;
            }
        }
#pragma unroll
        for (int off = 1; off <= 2; off <<= 1) {
            rs0 += __shfl_xor_sync(0xffffffffu, rs0, off);
            rs1 += __shfl_xor_sync(0xffffffffu, rs1, off);
        }
        l0 = l0 * al0 + rs0;
        l1 = l1 * al1 + rs1;
#pragma unroll
        for (int j = 0; j < 16; j++) {
            o[j][0] *= al0; o[j][1] *= al0;
            o[j][2] *= al1; o[j][3] *= al1;
        }

#pragma unroll
        for (int kc2 = 0; kc2 < 4; kc2++) {
            uint32_t phi[4], plo[4];
            phi[0] = packsplit(s[2 * kc2][0],     s[2 * kc2][1],     plo[0]);
            phi[1] = packsplit(s[2 * kc2][2],     s[2 * kc2][3],     plo[1]);
            phi[2] = packsplit(s[2 * kc2 + 1][0], s[2 * kc2 + 1][1], plo[2]);
            phi[3] = packsplit(s[2 * kc2 + 1][2], s[2 * kc2 + 1][3], plo[3]);
#pragma unroll
            for (int nt = 0; nt < 8; nt++) {
                const int sub = nt >> 1, cb = (nt & 1) * 2;
                uint32_t va = st + 32768 + sub * 4096
                            + swoff(kc2 * 16 + v_row, cb + v_cofs);
                uint32_t vhf[4], vlf[4];
                ldsm4t(vhf, va);
                ldsm4t(vlf, va + 16384);
#pragma unroll
                for (int su = 0; su < 2; su++) {
                    float* d = o[nt * 2 + su];
                    mma16816(d, phi, vhf + su * 2);
                    mma16816(d, phi, vlf + su * 2);
                    mma16816(d, plo, vhf + su * 2);
                }
            }
        }
    }

    float inv0 = 1.f / l0, inv1 = 1.f / l1;
#pragma unroll
    for (int j = 0; j < 16; j++) {
        int col = j * 8 + colq;
        size_t b0 = ((size_t)(bs + gi0) * NH + h) * HD + col;
        size_t b1 = ((size_t)(bs + gi1) * NH + h) * HD + col;
        uint32_t lo0, lo1v;
        uint32_t hi0 = packsplit(o[j][0] * inv0, o[j][1] * inv0, lo0);
        uint32_t hi1 = packsplit(o[j][2] * inv1, o[j][3] * inv1, lo1v);
        *(uint32_t*)(aoh + b0) = hi0;
        *(uint32_t*)(aol + b0) = lo0;
        *(uint32_t*)(aoh + b1) = hi1;
        *(uint32_t*)(aol + b1) = lo1v;
    }
}

// ---------------------------------------------------------------------------
extern "C" void kernel_launch(void* const* d_in, const int* in_sizes, int n_in,
                              void* d_out, int out_size)
{
    const float* x    = (const float*)d_in[0];
    const float* cosT = (const float*)d_in[1];
    const float* sinT = (const float*)d_in[2];
    const float* Wq   = (const float*)d_in[3];
    const float* Wk   = (const float*)d_in[4];
    const float* Wv   = (const float*)d_in[5];
    const float* Wo   = (const float*)d_in[6];
    float* out = (float*)d_out;

    void *pxh, *pxl, *paoh, *paol, *pwh, *pwl, *pwoh, *pwol;
    void *pqh, *pql, *pkh, *pkl, *pvh, *pvl;
    cudaGetSymbolAddress(&pxh, g_xh);   cudaGetSymbolAddress(&pxl, g_xl);
    cudaGetSymbolAddress(&paoh, g_aoh); cudaGetSymbolAddress(&paol, g_aol);
    cudaGetSymbolAddress(&pwh, g_wqkvh); cudaGetSymbolAddress(&pwl, g_wqkvl);
    cudaGetSymbolAddress(&pwoh, g_woh); cudaGetSymbolAddress(&pwol, g_wol);
    cudaGetSymbolAddress(&pqh, g_qh);  cudaGetSymbolAddress(&pql, g_ql);
    cudaGetSymbolAddress(&pkh, g_kh);  cudaGetSymbolAddress(&pkl, g_kl);
    cudaGetSymbolAddress(&pvh, g_vh);  cudaGetSymbolAddress(&pvl, g_vl);

    __nv_bfloat16 *xh = (__nv_bfloat16*)pxh,   *xl = (__nv_bfloat16*)pxl;
    __nv_bfloat16 *aoh = (__nv_bfloat16*)paoh, *aol = (__nv_bfloat16*)paol;
    __nv_bfloat16 *wh = (__nv_bfloat16*)pwh,   *wl = (__nv_bfloat16*)pwl;
    __nv_bfloat16 *woh = (__nv_bfloat16*)pwoh, *wol = (__nv_bfloat16*)pwol;
    __nv_bfloat16 *qhp = (__nv_bfloat16*)pqh,  *qlp = (__nv_bfloat16*)pql;
    __nv_bfloat16 *khp = (__nv_bfloat16*)pkh,  *klp = (__nv_bfloat16*)pkl;
    __nv_bfloat16 *vhp = (__nv_bfloat16*)pvh,  *vlp = (__nv_bfloat16*)pvl;

    split_all<<<(NSPLIT4 + 255) / 256, 256>>>(x, Wq, Wk, Wv, Wo,
                                              xh, xl, wh, wl, woh, wol);

    cudaFuncSetAttribute(gemm_qkv, cudaFuncAttributeMaxDynamicSharedMemorySize, GSMEM);
    cudaFuncSetAttribute(gemm_mma, cudaFuncAttributeMaxDynamicSharedMemorySize, GSMEM);

    gemm_qkv<<<dim3(NQKV / 128, MR / 128), 128, GSMEM>>>(
        xh, xl, wh, wl, cosT, sinT, qhp, qlp, khp, klp, vhp, vlp);

    cudaFuncSetAttribute(flash_mma, cudaFuncAttributeMaxDynamicSharedMemorySize, FLASH_SMEM);
    flash_mma<<<dim3(Ss / 128, NH, Bb), 256, FLASH_SMEM>>>(
        qhp, qlp, khp, klp, vhp, vlp, aoh, aol);

    gemm_mma<<<dim3(Ee / 128, MR / 128), 128, GSMEM>>>(aoh, aol, woh, wol, out, MR, Ee, Ee);
}